// round 15
// baseline (speedup 1.0000x reference)
#include <cuda_runtime.h>
#include <math.h>
#include <float.h>
#include <stdint.h>

// ----------------------------------------------------------------------------
// HierarchicalLoss R13:
//  - small_losses: lane-per-negative / warp-per-anchor via shared-staged
//    negative tiles (conflict-free padded), register prefetch, NO shuffle
//    reduce in hot loop (one Σexp butterfly at end).
//  - prep = norms + init merged (one launch fewer)
//  - mlm: plain loads (L2 persistence across graph replays)
// ----------------------------------------------------------------------------

#define INV_TEMP (1.0f / 0.07f)
#define ANCH 4
#define NEGT 32          // negatives per tile (= warp lanes)
#define NCH  12          // chunks of 64 floats covering D=768

__device__ float g_partial[4];     // [mlm_sum, -, -, -]
__device__ int   g_mlm_count;
__device__ int   g_label_stride;   // 1 = int32 labels, 2 = int64 labels
__device__ float g_invnorm[1024];  // inverse L2 norms for all small-matrix rows
__device__ float g_S[384];         // per-anchor exp-sums: line@0, quat@256, sonnet@320
__device__ float g_pos[384];       // per-anchor positive sims (line/quat)

// ---- kernel A: norms (warp-per-row) + last-block init/detect ---------------
__global__ __launch_bounds__(256) void prep_kernel(
    const float* p0, const float* p1, const float* p2, const float* p3,
    const float* p4, const float* p5, const float* p6,
    int c0, int c1, int c2, int c3, int c4, int c5, int c6, int D,
    const int* __restrict__ lbl32, int nrows, int nNormBlocks, int totalRows)
{
    if (blockIdx.x == (unsigned)nNormBlocks) {
        __shared__ int bad;
        int tid = threadIdx.x;
        if (tid == 0) bad = 0;
        __syncthreads();
        for (int i = tid; i < nrows / 2; i += blockDim.x) {
            int hi = lbl32[2 * i + 1];
            if (hi != 0 && hi != -1) bad = 1;
        }
        for (int i = tid; i < 384; i += blockDim.x) { g_S[i] = 0.0f; g_pos[i] = 0.0f; }
        __syncthreads();
        if (tid == 0) {
            g_label_stride = bad ? 1 : 2;
            g_partial[0] = 0.0f;
            g_mlm_count = 0;
        }
        return;
    }
    const float* ptrs[7] = {p0, p1, p2, p3, p4, p5, p6};
    int cnt[7] = {c0, c1, c2, c3, c4, c5, c6};
    int w = threadIdx.x >> 5, lane = threadIdx.x & 31;
    int gr = blockIdx.x * 8 + w;
    if (gr >= totalRows) return;
    int idx = gr, seg = 0;
    while (idx >= cnt[seg]) { idx -= cnt[seg]; seg++; }
    const float4* row = (const float4*)(ptrs[seg] + (size_t)idx * D);

    float4 r[6];
    #pragma unroll
    for (int p = 0; p < 6; p++) r[p] = row[lane + 32 * p];
    float s = 0.f;
    #pragma unroll
    for (int p = 0; p < 6; p++)
        s += r[p].x * r[p].x + r[p].y * r[p].y + r[p].z * r[p].z + r[p].w * r[p].w;
    #pragma unroll
    for (int o = 16; o; o >>= 1) s += __shfl_xor_sync(0xffffffffu, s, o);
    if (lane == 0) g_invnorm[gr] = 1.0f / fmaxf(sqrtf(s), 1e-12f);
}

// ---- kernel 1: MLM cross-entropy: exp-sum chains, plain loads --------------
__global__ __launch_bounds__(512) void mlm_kernel(
    const float* __restrict__ logits, const int* __restrict__ lbl32, int V)
{
    int row = blockIdx.x;
    int lbl = lbl32[(size_t)row * g_label_stride];
    if (lbl < 0) return;

    const float* __restrict__ x = logits + (size_t)row * V;
    int tid = threadIdx.x;

    float s0 = 0.f, s1 = 0.f, s2 = 0.f, s3 = 0.f;
    float s4 = 0.f, s5 = 0.f, s6 = 0.f, s7 = 0.f;

    int head = (((uintptr_t)x) & 15) ? 2 : 0;
    if (tid < head) s0 += __expf(x[tid]);

    const float4* __restrict__ x4 = (const float4*)(x + head);
    int n4 = (V - head) >> 2;
    int tail = (V - head) & 3;

    int i = tid;
    for (; i + 512 < n4; i += 1024) {
        float4 v0 = x4[i];
        float4 v1 = x4[i + 512];
        s0 += __expf(v0.x); s1 += __expf(v0.y);
        s2 += __expf(v0.z); s3 += __expf(v0.w);
        s4 += __expf(v1.x); s5 += __expf(v1.y);
        s6 += __expf(v1.z); s7 += __expf(v1.w);
    }
    for (; i < n4; i += 512) {
        float4 v0 = x4[i];
        s0 += __expf(v0.x); s1 += __expf(v0.y);
        s2 += __expf(v0.z); s3 += __expf(v0.w);
    }
    if (tid < tail) s4 += __expf(x[head + 4 * n4 + tid]);

    float S0 = ((s0 + s1) + (s2 + s3)) + ((s4 + s5) + (s6 + s7));
    for (int o = 16; o; o >>= 1) S0 += __shfl_xor_sync(0xffffffffu, S0, o);
    __shared__ float shs[16];
    int w = tid >> 5;
    if ((tid & 31) == 0) shs[w] = S0;
    __syncthreads();
    if (tid == 0) {
        float S = 0.f;
        #pragma unroll
        for (int k = 0; k < 16; k++) S += shs[k];
        float xl = __ldg(x + lbl);
        atomicAdd(&g_partial[0], logf(S) - xl);
        atomicAdd(&g_mlm_count, 1);
    }
}

// ---- kernel 2: contrastive exp-sums: lane-per-negative, warp-per-anchor ----
__global__ __launch_bounds__(128) void small_losses_kernel(
    const float* __restrict__ LA, const float* __restrict__ LP, const float* __restrict__ LN,
    const float* __restrict__ QA, const float* __restrict__ QP, const float* __restrict__ QN,
    const float* __restrict__ SE,
    int PL, int NL, int PQ, int NQ, int BS, int D,
    int oLA, int oLP, int oLN, int oQA, int oQP, int oQN, int oSE,
    int nTL, int nTQ, int nTS, int nbL, int nbQ)
{
    __shared__ float4 a_s4[ANCH * 192];        // 4 normalized anchors (12 KB)
    __shared__ float4 tile[NEGT * 17];         // 32 rows x 16 float4, stride 17 (8.7 KB)
    __shared__ float  invn_s[NEGT];

    int b = blockIdx.x;
    int tid = threadIdx.x;
    int w = tid >> 5, lane = tid & 31;

    const float* Arr; const float* Prr; const float* Nrr;
    const float* inva; const float* invp; const float* invn;
    int aT, nT_loc, Ncnt, Pcnt, gbase; bool sonnet = false;
    if (b < nbL) {
        Arr = LA; Prr = LP; Nrr = LN; Ncnt = NL; Pcnt = PL; gbase = 0;
        inva = g_invnorm + oLA; invp = g_invnorm + oLP; invn = g_invnorm + oLN;
        aT = b / nTL; nT_loc = b - aT * nTL;
    } else if (b < nbL + nbQ) {
        int lb = b - nbL;
        Arr = QA; Prr = QP; Nrr = QN; Ncnt = NQ; Pcnt = PQ; gbase = 256;
        inva = g_invnorm + oQA; invp = g_invnorm + oQP; invn = g_invnorm + oQN;
        aT = lb / nTQ; nT_loc = lb - aT * nTQ;
    } else {
        int lb = b - nbL - nbQ;
        Arr = SE; Prr = SE; Nrr = SE; Ncnt = BS; Pcnt = BS; gbase = 320;
        inva = g_invnorm + oSE; invp = g_invnorm + oSE; invn = g_invnorm + oSE;
        aT = lb / nTS; nT_loc = lb - aT * nTS;
        sonnet = true;
    }
    int i0 = aT * ANCH;
    int nA = min(ANCH, Pcnt - i0);
    int jt0 = nT_loc * NEGT;

    // stage normalized anchors (coalesced). Missing anchors (nA<4): stage
    // anchor 0's data (harmless; outputs masked) to avoid garbage/NaN.
    for (int t = tid; t < ANCH * 192; t += 128) {
        int a = t / 192, k = t - a * 192;
        int ai = i0 + (a < nA ? a : 0);
        float ia = inva[ai];
        float4 v = ((const float4*)(Arr + (size_t)ai * D))[k];
        a_s4[t] = make_float4(v.x * ia, v.y * ia, v.z * ia, v.w * ia);
    }
    if (tid < NEGT) invn_s[tid] = invn[min(jt0 + tid, Ncnt - 1)];
    __syncthreads();

    // positives (infonce, anchor-tile's first negative-tile only)
    if (!sonnet && nT_loc == 0 && w < nA) {
        const float4* Prow = (const float4*)(Prr + (size_t)(i0 + w) * D);
        float4 r[6];
        #pragma unroll
        for (int p = 0; p < 6; p++) r[p] = Prow[lane + 32 * p];
        float d = 0.f;
        #pragma unroll
        for (int p = 0; p < 6; p++) {
            float4 a = a_s4[w * 192 + lane + 32 * p];
            d += a.x * r[p].x + a.y * r[p].y + a.z * r[p].z + a.w * r[p].w;
        }
        #pragma unroll
        for (int o = 16; o; o >>= 1) d += __shfl_xor_sync(0xffffffffu, d, o);
        if (lane == 0) g_pos[gbase + i0 + w] = d * invp[i0 + w] * INV_TEMP;
    }

    // ---- main loop: chunks of 64 floats (16 float4) over D ----
    // stage mapping: thread t -> row r=t>>2, quarter q=t&3 (4 float4 each)
    int sr = tid >> 2, sq = tid & 3;
    int srow = min(jt0 + sr, Ncnt - 1);
    const float4* grow = (const float4*)(Nrr + (size_t)srow * D);

    float d = 0.f;                 // lane's dot: anchor (i0+w) . negative (jt0+lane)

    // prefetch chunk 0
    float4 pre[4];
    #pragma unroll
    for (int i = 0; i < 4; i++) pre[i] = grow[sq * 4 + i];
    #pragma unroll
    for (int i = 0; i < 4; i++) tile[sr * 17 + sq * 4 + i] = pre[i];
    __syncthreads();

    for (int c = 0; c < NCH; c++) {
        // prefetch next chunk into registers (no smem conflict with readers)
        if (c + 1 < NCH) {
            #pragma unroll
            for (int i = 0; i < 4; i++) pre[i] = grow[(c + 1) * 16 + sq * 4 + i];
        }
        // compute chunk c: lane reads its row (stride-17, conflict-free),
        // anchor read is a broadcast
        #pragma unroll
        for (int k = 0; k < 16; k++) {
            float4 nv = tile[lane * 17 + k];
            float4 av = a_s4[w * 192 + c * 16 + k];
            d += av.x * nv.x + av.y * nv.y + av.z * nv.z + av.w * nv.w;
        }
        __syncthreads();
        if (c + 1 < NCH) {
            #pragma unroll
            for (int i = 0; i < 4; i++) tile[sr * 17 + sq * 4 + i] = pre[i];
            __syncthreads();
        }
    }

    // exp + warp-sum (single butterfly), masked for OOB lanes / anchors
    float se = 0.f;
    if (jt0 + lane < Ncnt) se = __expf(d * invn_s[lane] * INV_TEMP);
    #pragma unroll
    for (int o = 16; o; o >>= 1) se += __shfl_xor_sync(0xffffffffu, se, o);
    if (lane == 0 && w < nA) atomicAdd(&g_S[gbase + i0 + w], se);
}

// ---- kernel 3: finalize: per-anchor log + weighted combination -------------
__global__ __launch_bounds__(256) void finalize_kernel(
    float* __restrict__ out, int PL, int PQ, int BS)
{
    int tid = threadIdx.x;
    float accL = 0.f, accQ = 0.f, accS = 0.f;
    for (int i = tid; i < PL; i += 256) {
        float p = g_pos[i];
        accL += logf(g_S[i] + __expf(p)) - p;
    }
    for (int i = tid; i < PQ; i += 256) {
        float p = g_pos[256 + i];
        accQ += logf(g_S[256 + i] + __expf(p)) - p;
    }
    for (int i = tid; i < BS; i += 256) {
        accS += logf(g_S[320 + i]) - INV_TEMP;   // self term included in sum
    }
    #pragma unroll
    for (int o = 16; o; o >>= 1) {
        accL += __shfl_xor_sync(0xffffffffu, accL, o);
        accQ += __shfl_xor_sync(0xffffffffu, accQ, o);
        accS += __shfl_xor_sync(0xffffffffu, accS, o);
    }
    __shared__ float rl[8], rq[8], rs[8];
    int w = tid >> 5;
    if ((tid & 31) == 0) { rl[w] = accL; rq[w] = accQ; rs[w] = accS; }
    __syncthreads();
    if (tid == 0) {
        float L = 0.f, Q = 0.f, S = 0.f;
        #pragma unroll
        for (int k = 0; k < 8; k++) { L += rl[k]; Q += rq[k]; S += rs[k]; }
        float mlm = g_partial[0] / fmaxf((float)g_mlm_count, 1.0f);
        out[0] = 0.5f * mlm
               + 0.2f * L / (float)PL
               + 0.2f * Q / (float)PQ
               + 0.1f * S / (float)BS;
    }
}

// ----------------------------------------------------------------------------
extern "C" void kernel_launch(void* const* d_in, const int* in_sizes, int n_in,
                              void* d_out, int out_size)
{
    const float* mlm_logits = (const float*)d_in[0];
    const int*   labels     = (const int*)d_in[1];
    const float* LA = (const float*)d_in[2];
    const float* LP = (const float*)d_in[3];
    const float* LN = (const float*)d_in[4];
    const float* QA = (const float*)d_in[5];
    const float* QP = (const float*)d_in[6];
    const float* QN = (const float*)d_in[7];
    const float* SE = (const float*)d_in[8];

    const int D  = 768;
    int NR  = in_sizes[1];
    int V   = in_sizes[0] / NR;
    int PL  = in_sizes[2] / D;
    int PLp = in_sizes[3] / D;
    int NL  = in_sizes[4] / D;
    int PQ  = in_sizes[5] / D;
    int PQp = in_sizes[6] / D;
    int NQ  = in_sizes[7] / D;
    int BS  = in_sizes[8] / D;

    int oLA = 0;
    int oLP = oLA + PL;
    int oLN = oLP + PLp;
    int oQA = oLN + NL;
    int oQP = oQA + PQ;
    int oQN = oQP + PQp;
    int oSE = oQN + NQ;
    int totalRows = oSE + BS;

    int aTL = (PL + ANCH - 1) / ANCH, nTL = (NL + NEGT - 1) / NEGT;
    int aTQ = (PQ + ANCH - 1) / ANCH, nTQ = (NQ + NEGT - 1) / NEGT;
    int aTS = (BS + ANCH - 1) / ANCH, nTS = (BS + NEGT - 1) / NEGT;
    int nbL = aTL * nTL;
    int nbQ = aTQ * nTQ;
    int nbS = aTS * nTS;

    int nNormBlocks = (totalRows + 7) / 8;

    prep_kernel<<<nNormBlocks + 1, 256>>>(LA, LP, LN, QA, QP, QN, SE,
                                          PL, PLp, NL, PQ, PQp, NQ, BS, D,
                                          labels, NR, nNormBlocks, totalRows);
    mlm_kernel<<<NR, 512>>>(mlm_logits, labels, V);
    small_losses_kernel<<<nbL + nbQ + nbS, 128>>>(LA, LP, LN, QA, QP, QN, SE,
                                                  PL, NL, PQ, NQ, BS, D,
                                                  oLA, oLP, oLN, oQA, oQP, oQN, oSE,
                                                  nTL, nTQ, nTS, nbL, nbQ);
    finalize_kernel<<<1, 256>>>((float*)d_out, PL, PQ, BS);
}

// round 16
// speedup vs baseline: 1.0059x; 1.0059x over previous
#include <cuda_runtime.h>
#include <math.h>
#include <float.h>
#include <stdint.h>

// ----------------------------------------------------------------------------
// HierarchicalLoss R16 = R12 (verified 32.8us) with overhead removed:
//  - finalize folded into small_losses via threadfence-reduction ticket
//    (last block computes the ~300-element epilogue with __logf)
//  - init merged into norms (prep kernel)
//  - 3 launches total; mlm/small hot paths byte-identical to R12
// ----------------------------------------------------------------------------

#define INV_TEMP (1.0f / 0.07f)
#define ANCH 4
#define NEGT 32          // negatives per tile

__device__ float g_partial[4];     // [mlm_sum, -, -, -]
__device__ int   g_mlm_count;
__device__ int   g_label_stride;   // 1 = int32 labels, 2 = int64 labels
__device__ float g_invnorm[1024];  // inverse L2 norms for all small-matrix rows
__device__ float g_S[384];         // per-anchor exp-sums: line@0, quat@256, sonnet@320
__device__ float g_pos[384];       // per-anchor positive sims (line/quat)
__device__ int   g_done;           // completion ticket for folded finalize

// ---- kernel A: norms (warp-per-row) + last-block init/detect ---------------
__global__ __launch_bounds__(256) void prep_kernel(
    const float* p0, const float* p1, const float* p2, const float* p3,
    const float* p4, const float* p5, const float* p6,
    int c0, int c1, int c2, int c3, int c4, int c5, int c6, int D,
    const int* __restrict__ lbl32, int nrows, int nNormBlocks, int totalRows)
{
    if (blockIdx.x == (unsigned)nNormBlocks) {
        __shared__ int bad;
        int tid = threadIdx.x;
        if (tid == 0) bad = 0;
        __syncthreads();
        for (int i = tid; i < nrows / 2; i += blockDim.x) {
            int hi = lbl32[2 * i + 1];
            if (hi != 0 && hi != -1) bad = 1;
        }
        for (int i = tid; i < 384; i += blockDim.x) { g_S[i] = 0.0f; g_pos[i] = 0.0f; }
        __syncthreads();
        if (tid == 0) {
            g_label_stride = bad ? 1 : 2;
            g_partial[0] = 0.0f;
            g_mlm_count = 0;
            g_done = 0;
        }
        return;
    }
    const float* ptrs[7] = {p0, p1, p2, p3, p4, p5, p6};
    int cnt[7] = {c0, c1, c2, c3, c4, c5, c6};
    int w = threadIdx.x >> 5, lane = threadIdx.x & 31;
    int gr = blockIdx.x * 8 + w;
    if (gr >= totalRows) return;
    int idx = gr, seg = 0;
    while (idx >= cnt[seg]) { idx -= cnt[seg]; seg++; }
    const float4* row = (const float4*)(ptrs[seg] + (size_t)idx * D);

    float4 r[6];
    #pragma unroll
    for (int p = 0; p < 6; p++) r[p] = row[lane + 32 * p];
    float s = 0.f;
    #pragma unroll
    for (int p = 0; p < 6; p++)
        s += r[p].x * r[p].x + r[p].y * r[p].y + r[p].z * r[p].z + r[p].w * r[p].w;
    #pragma unroll
    for (int o = 16; o; o >>= 1) s += __shfl_xor_sync(0xffffffffu, s, o);
    if (lane == 0) g_invnorm[gr] = 1.0f / fmaxf(sqrtf(s), 1e-12f);
}

// ---- kernel 1: MLM cross-entropy (R12 verbatim) ----------------------------
__global__ __launch_bounds__(512) void mlm_kernel(
    const float* __restrict__ logits, const int* __restrict__ lbl32, int V)
{
    int row = blockIdx.x;
    int lbl = lbl32[(size_t)row * g_label_stride];
    if (lbl < 0) return;

    const float* __restrict__ x = logits + (size_t)row * V;
    int tid = threadIdx.x;

    float s0 = 0.f, s1 = 0.f, s2 = 0.f, s3 = 0.f;
    float s4 = 0.f, s5 = 0.f, s6 = 0.f, s7 = 0.f;

    int head = (((uintptr_t)x) & 15) ? 2 : 0;
    if (tid < head) s0 += __expf(x[tid]);

    const float4* __restrict__ x4 = (const float4*)(x + head);
    int n4 = (V - head) >> 2;
    int tail = (V - head) & 3;

    int i = tid;
    for (; i + 512 < n4; i += 1024) {
        float4 v0 = __ldcs(x4 + i);
        float4 v1 = __ldcs(x4 + i + 512);
        s0 += __expf(v0.x); s1 += __expf(v0.y);
        s2 += __expf(v0.z); s3 += __expf(v0.w);
        s4 += __expf(v1.x); s5 += __expf(v1.y);
        s6 += __expf(v1.z); s7 += __expf(v1.w);
    }
    for (; i < n4; i += 512) {
        float4 v0 = __ldcs(x4 + i);
        s0 += __expf(v0.x); s1 += __expf(v0.y);
        s2 += __expf(v0.z); s3 += __expf(v0.w);
    }
    if (tid < tail) s4 += __expf(x[head + 4 * n4 + tid]);

    float S0 = ((s0 + s1) + (s2 + s3)) + ((s4 + s5) + (s6 + s7));
    for (int o = 16; o; o >>= 1) S0 += __shfl_xor_sync(0xffffffffu, S0, o);
    __shared__ float shs[16];
    int w = tid >> 5;
    if ((tid & 31) == 0) shs[w] = S0;
    __syncthreads();
    if (tid == 0) {
        float S = 0.f;
        #pragma unroll
        for (int k = 0; k < 16; k++) S += shs[k];
        float xl = __ldg(x + lbl);
        atomicAdd(&g_partial[0], logf(S) - xl);
        atomicAdd(&g_mlm_count, 1);
    }
}

// ---- kernel 2: contrastive exp-sums (R12 verbatim) + folded finalize -------
__global__ __launch_bounds__(128) void small_losses_kernel(
    const float* __restrict__ LA, const float* __restrict__ LP, const float* __restrict__ LN,
    const float* __restrict__ QA, const float* __restrict__ QP, const float* __restrict__ QN,
    const float* __restrict__ SE,
    int PL, int NL, int PQ, int NQ, int BS, int D,
    int oLA, int oLP, int oLN, int oQA, int oQP, int oQN, int oSE,
    int nTL, int nTQ, int nTS, int nbL, int nbQ,
    float* __restrict__ out, int nTotalBlocks)
{
    __shared__ float4 a_s4[ANCH * 192];   // 4 normalized anchors
    __shared__ float  invn_s[NEGT];

    int b = blockIdx.x;
    int tid = threadIdx.x;

    const float* Arr; const float* Prr; const float* Nrr;
    const float* inva; const float* invp; const float* invn;
    int aT, nT_loc, Ncnt, Pcnt, gbase; bool sonnet = false;
    if (b < nbL) {
        Arr = LA; Prr = LP; Nrr = LN; Ncnt = NL; Pcnt = PL; gbase = 0;
        inva = g_invnorm + oLA; invp = g_invnorm + oLP; invn = g_invnorm + oLN;
        aT = b / nTL; nT_loc = b - aT * nTL;
    } else if (b < nbL + nbQ) {
        int lb = b - nbL;
        Arr = QA; Prr = QP; Nrr = QN; Ncnt = NQ; Pcnt = PQ; gbase = 256;
        inva = g_invnorm + oQA; invp = g_invnorm + oQP; invn = g_invnorm + oQN;
        aT = lb / nTQ; nT_loc = lb - aT * nTQ;
    } else {
        int lb = b - nbL - nbQ;
        Arr = SE; Prr = SE; Nrr = SE; Ncnt = BS; Pcnt = BS; gbase = 320;
        inva = g_invnorm + oSE; invp = g_invnorm + oSE; invn = g_invnorm + oSE;
        aT = lb / nTS; nT_loc = lb - aT * nTS;
        sonnet = true;
    }
    int i0 = aT * ANCH;
    int nA = min(ANCH, Pcnt - i0);
    int jt0 = nT_loc * NEGT;

    // stage normalized anchors (128 threads, coalesced)
    for (int t = tid; t < nA * 192; t += 128) {
        int a = t / 192, k = t - a * 192;
        float ia = inva[i0 + a];
        float4 v = ((const float4*)(Arr + (size_t)(i0 + a) * D))[k];
        a_s4[a * 192 + k] = make_float4(v.x * ia, v.y * ia, v.z * ia, v.w * ia);
    }
    if (tid < NEGT && jt0 + tid < Ncnt) invn_s[tid] = invn[jt0 + tid];
    __syncthreads();

    int w = tid >> 5, lane = tid & 31;

    // positives (infonce, tile 0 only): warp a -> anchor a; store to g_pos
    if (!sonnet && nT_loc == 0 && w < nA) {
        const float4* Prow = (const float4*)(Prr + (size_t)(i0 + w) * D);
        float4 r[6];
        #pragma unroll
        for (int p = 0; p < 6; p++) r[p] = Prow[lane + 32 * p];
        float d = 0.f;
        #pragma unroll
        for (int p = 0; p < 6; p++) {
            float4 a = a_s4[w * 192 + lane + 32 * p];
            d += a.x * r[p].x + a.y * r[p].y + a.z * r[p].z + a.w * r[p].w;
        }
        #pragma unroll
        for (int o = 16; o; o >>= 1) d += __shfl_xor_sync(0xffffffffu, d, o);
        if (lane == 0) g_pos[gbase + i0 + w] = d * invp[i0 + w] * INV_TEMP;
    }

    // negatives: warp handles 8 rows of this 32-row tile, 4 rows in flight,
    // each row reused for all 4 anchors. Partial exp-sums accumulated locally.
    int jbeg = jt0 + w * 8;
    int jend = min(jbeg + 8, Ncnt);
    float se0 = 0.f, se1 = 0.f, se2 = 0.f, se3 = 0.f;

    for (int j = jbeg; j < jend; j += 4) {
        int nv = jend - j;
        int j1 = j + (nv > 1 ? 1 : 0);
        int j2 = j + (nv > 2 ? 2 : 0);
        int j3 = j + (nv > 3 ? 3 : 0);
        const float4* n0 = (const float4*)(Nrr + (size_t)j  * D);
        const float4* n1 = (const float4*)(Nrr + (size_t)j1 * D);
        const float4* n2 = (const float4*)(Nrr + (size_t)j2 * D);
        const float4* n3 = (const float4*)(Nrr + (size_t)j3 * D);

        float4 r[24];
        #pragma unroll
        for (int p = 0; p < 6; p++) {
            int kk = lane + 32 * p;
            r[p]      = n0[kk];
            r[6 + p]  = n1[kk];
            r[12 + p] = n2[kk];
            r[18 + p] = n3[kk];
        }

        float d[16];
        #pragma unroll
        for (int q = 0; q < 16; q++) d[q] = 0.f;
        #pragma unroll
        for (int p = 0; p < 6; p++) {
            int kk = lane + 32 * p;
            #pragma unroll
            for (int a = 0; a < ANCH; a++) {
                float4 av = a_s4[a * 192 + kk];
                d[a * 4 + 0] += av.x * r[p].x      + av.y * r[p].y      + av.z * r[p].z      + av.w * r[p].w;
                d[a * 4 + 1] += av.x * r[6 + p].x  + av.y * r[6 + p].y  + av.z * r[6 + p].z  + av.w * r[6 + p].w;
                d[a * 4 + 2] += av.x * r[12 + p].x + av.y * r[12 + p].y + av.z * r[12 + p].z + av.w * r[12 + p].w;
                d[a * 4 + 3] += av.x * r[18 + p].x + av.y * r[18 + p].y + av.z * r[18 + p].z + av.w * r[18 + p].w;
            }
        }
        #pragma unroll
        for (int o = 16; o; o >>= 1)
            #pragma unroll
            for (int q = 0; q < 16; q++)
                d[q] += __shfl_xor_sync(0xffffffffu, d[q], o);

        float c0 = invn_s[j  - jt0] * INV_TEMP;
        float c1 = invn_s[j1 - jt0] * INV_TEMP;
        float c2 = invn_s[j2 - jt0] * INV_TEMP;
        float c3 = invn_s[j3 - jt0] * INV_TEMP;
        se0 += __expf(d[0] * c0);
        se1 += __expf(d[4] * c0);
        se2 += __expf(d[8] * c0);
        se3 += __expf(d[12] * c0);
        if (nv > 1) { se0 += __expf(d[1] * c1);  se1 += __expf(d[5] * c1);
                      se2 += __expf(d[9] * c1);  se3 += __expf(d[13] * c1); }
        if (nv > 2) { se0 += __expf(d[2] * c2);  se1 += __expf(d[6] * c2);
                      se2 += __expf(d[10] * c2); se3 += __expf(d[14] * c2); }
        if (nv > 3) { se0 += __expf(d[3] * c3);  se1 += __expf(d[7] * c3);
                      se2 += __expf(d[11] * c3); se3 += __expf(d[15] * c3); }
    }

    if (lane == 0 && jbeg < jend) {
        if (nA > 0) atomicAdd(&g_S[gbase + i0 + 0], se0);
        if (nA > 1) atomicAdd(&g_S[gbase + i0 + 1], se1);
        if (nA > 2) atomicAdd(&g_S[gbase + i0 + 2], se2);
        if (nA > 3) atomicAdd(&g_S[gbase + i0 + 3], se3);
    }

    // ---- folded finalize: last block to finish does the epilogue ----------
    __threadfence();
    __syncthreads();
    __shared__ int is_last;
    if (tid == 0) is_last = (atomicAdd(&g_done, 1) == nTotalBlocks - 1);
    __syncthreads();
    if (!is_last) return;

    float accL = 0.f, accQ = 0.f, accS = 0.f;
    for (int i = tid; i < PL; i += 128) {
        float p = g_pos[i];
        accL += __logf(g_S[i] + __expf(p)) - p;
    }
    for (int i = tid; i < PQ; i += 128) {
        float p = g_pos[256 + i];
        accQ += __logf(g_S[256 + i] + __expf(p)) - p;
    }
    for (int i = tid; i < BS; i += 128) {
        accS += __logf(g_S[320 + i]) - INV_TEMP;   // self term included in sum
    }
    float acc = accL * (0.2f / (float)PL)
              + accQ * (0.2f / (float)PQ)
              + accS * (0.1f / (float)BS);
    #pragma unroll
    for (int o = 16; o; o >>= 1) acc += __shfl_xor_sync(0xffffffffu, acc, o);
    __shared__ float rfin[4];
    if ((tid & 31) == 0) rfin[tid >> 5] = acc;
    __syncthreads();
    if (tid == 0) {
        float T = rfin[0] + rfin[1] + rfin[2] + rfin[3];
        float mlm = g_partial[0] / fmaxf((float)g_mlm_count, 1.0f);
        out[0] = 0.5f * mlm + T;
        g_done = 0;    // reset ticket for next graph replay
    }
}

// ----------------------------------------------------------------------------
extern "C" void kernel_launch(void* const* d_in, const int* in_sizes, int n_in,
                              void* d_out, int out_size)
{
    const float* mlm_logits = (const float*)d_in[0];
    const int*   labels     = (const int*)d_in[1];
    const float* LA = (const float*)d_in[2];
    const float* LP = (const float*)d_in[3];
    const float* LN = (const float*)d_in[4];
    const float* QA = (const float*)d_in[5];
    const float* QP = (const float*)d_in[6];
    const float* QN = (const float*)d_in[7];
    const float* SE = (const float*)d_in[8];

    const int D  = 768;
    int NR  = in_sizes[1];
    int V   = in_sizes[0] / NR;
    int PL  = in_sizes[2] / D;
    int PLp = in_sizes[3] / D;
    int NL  = in_sizes[4] / D;
    int PQ  = in_sizes[5] / D;
    int PQp = in_sizes[6] / D;
    int NQ  = in_sizes[7] / D;
    int BS  = in_sizes[8] / D;

    int oLA = 0;
    int oLP = oLA + PL;
    int oLN = oLP + PLp;
    int oQA = oLN + NL;
    int oQP = oQA + PQ;
    int oQN = oQP + PQp;
    int oSE = oQN + NQ;
    int totalRows = oSE + BS;

    int aTL = (PL + ANCH - 1) / ANCH, nTL = (NL + NEGT - 1) / NEGT;
    int aTQ = (PQ + ANCH - 1) / ANCH, nTQ = (NQ + NEGT - 1) / NEGT;
    int aTS = (BS + ANCH - 1) / ANCH, nTS = (BS + NEGT - 1) / NEGT;
    int nbL = aTL * nTL;
    int nbQ = aTQ * nTQ;
    int nbS = aTS * nTS;
    int nTotal = nbL + nbQ + nbS;

    int nNormBlocks = (totalRows + 7) / 8;

    prep_kernel<<<nNormBlocks + 1, 256>>>(LA, LP, LN, QA, QP, QN, SE,
                                          PL, PLp, NL, PQ, PQp, NQ, BS, D,
                                          labels, NR, nNormBlocks, totalRows);
    mlm_kernel<<<NR, 512>>>(mlm_logits, labels, V);
    small_losses_kernel<<<nTotal, 128>>>(LA, LP, LN, QA, QP, QN, SE,
                                         PL, NL, PQ, NQ, BS, D,
                                         oLA, oLP, oLN, oQA, oQP, oQN, oSE,
                                         nTL, nTQ, nTS, nbL, nbQ,
                                         (float*)d_out, nTotal);
}